// round 2
// baseline (speedup 1.0000x reference)
#include <cuda_runtime.h>
#include <cstddef>

#define BB 4
#define LL 2048
#define HH 8
#define DD 64
#define SK 40
#define NT 40
#define BHN 32          // B*H
#define NSPLIT 16
#define CHUNK 128       // keys per split block in attn
#define SCALE 0.125f    // 1/sqrt(64)

#define CK 384          // keys per strip (smem tile rows)
#define NKC 6           // ceil(2048/384)
#define CAPSTRIP 20480  // entry capacity per strip (mean ~15360)
#define LQ 4            // l-quarters per gather block
#define LRANGE 512      // LL/LQ

// ---------------- scratch (device globals) ----------------
__device__ int   g_is64;
__device__ int   g_cnt[NKC * LL];
__device__ int   g_off[NKC * (LL + 1)];
__device__ int   g_cur[NKC * LL];
__device__ int   g_list[NKC * CAPSTRIP];
__device__ float g_dots[BHN * LL * SK];         // 10.5 MB
__device__ float g_M[BHN * LL];
__device__ int   g_top[BHN * NT];
__device__ float g_pm[BHN * NSPLIT * NT];
__device__ float g_pl[BHN * NSPLIT * NT];
__device__ float g_po[BHN * NSPLIT * NT * DD];  // 5.24 MB

// ---------------- detect index dtype (int64 vs int32) ----------------
__global__ void detect_idx_kernel(const long long* __restrict__ idx64) {
    int ok = 1;
    for (int i = threadIdx.x; i < 512; i += 32) {
        long long v = idx64[i];
        if (v < 0 || v >= LL) ok = 0;
    }
    unsigned m = __ballot_sync(0xffffffffu, ok);
    if (threadIdx.x == 0) g_is64 = (m == 0xffffffffu) ? 1 : 0;
}

// ---------------- inverted-list build ----------------
__global__ void zero_cnt_kernel() {
    int i = blockIdx.x * 256 + threadIdx.x;   // grid covers NKC*LL exactly
    g_cnt[i] = 0;
}

__global__ void count_kernel(const void* __restrict__ idxbuf) {
    int e = blockIdx.x * 256 + threadIdx.x;   // 81920 entries exactly
    int l = e / SK;
    int j = g_is64 ? (int)((const long long*)idxbuf)[e]
                   : ((const int*)idxbuf)[e];
    atomicAdd(&g_cnt[(j / CK) * LL + l], 1);
}

__global__ void scan_kernel() {
    __shared__ int part[256];
    int kc = blockIdx.x, t = threadIdx.x;
    int loc[8]; int sum = 0;
#pragma unroll
    for (int i = 0; i < 8; i++) { loc[i] = sum; sum += g_cnt[kc * LL + t * 8 + i]; }
    part[t] = sum;
    __syncthreads();
    for (int o = 1; o < 256; o <<= 1) {
        int v = (t >= o) ? part[t - o] : 0;
        __syncthreads();
        part[t] += v;
        __syncthreads();
    }
    int excl = (t == 0) ? 0 : part[t - 1];
    int base = kc * CAPSTRIP;
#pragma unroll
    for (int i = 0; i < 8; i++) {
        int o = base + excl + loc[i];
        g_off[kc * (LL + 1) + t * 8 + i] = o;
        g_cur[kc * LL + t * 8 + i] = o;
    }
    if (t == 255) g_off[kc * (LL + 1) + LL] = base + part[255];
}

__global__ void scatter_kernel(const void* __restrict__ idxbuf) {
    int e = blockIdx.x * 256 + threadIdx.x;
    int l = e / SK, s = e % SK;
    int j = g_is64 ? (int)((const long long*)idxbuf)[e]
                   : ((const int*)idxbuf)[e];
    int kc = j / CK;
    int pos = atomicAdd(&g_cur[kc * LL + l], 1);
    g_list[pos] = (s << 11) | j;   // (l,s) slot fixed -> deterministic output
}

// ---------------- gather dots: block = (bh, strip, l-quarter) ----------------
__global__ void gather_dots_kernel(const float* __restrict__ Q,
                                   const float* __restrict__ K) {
    extern __shared__ float Ks[];                  // CK*64 floats = 96 KB
    int bid = blockIdx.x;
    int bh = bid / (NKC * LQ);
    int r  = bid % (NKC * LQ);
    int kc = r / LQ, lq = r % LQ;
    int b = bh >> 3, h = bh & 7;
    int t = threadIdx.x;
    int rows = min(CK, LL - kc * CK);

    // stage K strip (coalesced float4)
    for (int i = t; i < rows * 16; i += 256) {
        int rr = i >> 4, c4 = i & 15;
        ((float4*)Ks)[(rr << 4) + c4] =
            ((const float4*)(K + (((size_t)(b * LL + kc * CK + rr) * HH + h) << 6)))[c4];
    }
    __syncthreads();

    int w = t >> 5, lane = t & 31;
    const int* offp = g_off + kc * (LL + 1);
    const float2* Ks2 = (const float2*)Ks;
    int l0 = lq * LRANGE + w * (LRANGE / 8);

    for (int l = l0; l < l0 + (LRANGE / 8); l++) {
        int a = offp[l], ee = offp[l + 1];
        if (a == ee) continue;
        const float2 q = *(const float2*)(Q + (((size_t)(b * LL + l) * HH + h) << 6) + (lane << 1));
        float* dbase = g_dots + ((size_t)(bh * LL + l)) * SK;
        for (int pos = a; pos < ee; pos += 8) {
            float v[8]; int sidx[8];
#pragma unroll
            for (int u = 0; u < 8; u++) {
                int pp = g_list[min(pos + u, ee - 1)];   // pad by replicating last
                sidx[u] = pp >> 11;
                int jl = (pp & 2047) - kc * CK;
                float2 k = Ks2[(jl << 5) + lane];
                v[u] = fmaf(q.x, k.x, q.y * k.y);
            }
#pragma unroll
            for (int u = 0; u < 8; u++) {
                v[u] += __shfl_xor_sync(0xffffffffu, v[u], 16);
                v[u] += __shfl_xor_sync(0xffffffffu, v[u], 8);
                v[u] += __shfl_xor_sync(0xffffffffu, v[u], 4);
                v[u] += __shfl_xor_sync(0xffffffffu, v[u], 2);
                v[u] += __shfl_xor_sync(0xffffffffu, v[u], 1);
            }
            if (lane == 0) {
#pragma unroll
                for (int u = 0; u < 8; u++) dbase[sidx[u]] = v[u];
            }
        }
    }
}

// ---------------- M = max_s(dots) - sum_s(dots)/L ----------------
__global__ void m_reduce_kernel() {
    int t = blockIdx.x * 256 + threadIdx.x;        // 65536 = BHN*LL
    const float4* dp = (const float4*)(g_dots + (size_t)t * SK);
    float mx = -3e38f, sm = 0.f;
#pragma unroll
    for (int i = 0; i < 10; i++) {
        float4 d = dp[i];
        mx = fmaxf(mx, fmaxf(fmaxf(d.x, d.y), fmaxf(d.z, d.w)));
        sm += d.x + d.y + d.z + d.w;
    }
    g_M[t] = mx - sm * (1.0f / (float)LL);
}

// ---------------- top-40 per bh: warp kernel, tie -> lower index ----------------
__global__ void topk_kernel() {
    __shared__ float sM[LL];
    int bh = blockIdx.x, lane = threadIdx.x;       // 32 threads
    for (int i = lane; i < LL; i += 32) sM[i] = g_M[bh * LL + i];
    __syncwarp();

    // per-lane segment [lane*64, lane*64+64)
    float bv = -3e38f; int bi = lane * 64;
    for (int i = 0; i < 64; i++) {
        float x = sM[lane * 64 + i];
        if (x > bv) { bv = x; bi = lane * 64 + i; }
    }
    for (int it = 0; it < NT; it++) {
        unsigned uv = __float_as_uint(bv);
        uv ^= (uv >> 31) ? 0xffffffffu : 0x80000000u;
        unsigned long long key = ((unsigned long long)uv << 32) | (unsigned)(LL - 1 - bi);
#pragma unroll
        for (int o = 16; o; o >>= 1) {
            unsigned long long ok = __shfl_xor_sync(0xffffffffu, key, o);
            if (ok > key) key = ok;
        }
        int wi = LL - 1 - (int)(key & 0xffffffffu);
        if (lane == 0) { g_top[bh * NT + it] = wi; sM[wi] = -3e38f; }
        __syncwarp();

        int seg = wi >> 6;
        // cooperative rescan of popped segment
        float x0 = sM[(seg << 6) + lane];
        float x1 = sM[(seg << 6) + 32 + lane];
        float rv; int ri;
        if (x0 >= x1) { rv = x0; ri = (seg << 6) + lane; }
        else          { rv = x1; ri = (seg << 6) + 32 + lane; }
        unsigned ru = __float_as_uint(rv);
        ru ^= (ru >> 31) ? 0xffffffffu : 0x80000000u;
        unsigned long long rkey = ((unsigned long long)ru << 32) | (unsigned)(LL - 1 - ri);
#pragma unroll
        for (int o = 16; o; o >>= 1) {
            unsigned long long ok = __shfl_xor_sync(0xffffffffu, rkey, o);
            if (ok > rkey) rkey = ok;
        }
        if (lane == seg) {
            unsigned nu = (unsigned)(rkey >> 32);
            nu = (nu & 0x80000000u) ? (nu ^ 0x80000000u) : ~nu;  // inverse ord map
            bv = __uint_as_float(nu);
            bi = LL - 1 - (int)(rkey & 0xffffffffu);
        }
        __syncwarp();
    }
}

// ---------------- split-K attention (unchanged) ----------------
__global__ void attn_kernel(const float* __restrict__ Q,
                            const float* __restrict__ K,
                            const float* __restrict__ V) {
    extern __shared__ float smem[];
    int bh = blockIdx.x / NSPLIT, split = blockIdx.x % NSPLIT;
    int b = bh >> 3, h = bh & 7;
    int t = threadIdx.x;

    float* Qs = smem;
    float* Kt = Qs + NT * DD;
    float* Vs = Kt + 64 * 132;
    float* Ss = Vs + CHUNK * DD;

    for (int i = t; i < NT * DD; i += 256) {
        int u = i >> 6, d = i & 63;
        int ql = g_top[bh * NT + u];
        Qs[i] = Q[(((size_t)(b * LL + ql) * HH + h) << 6) + d];
    }
    int key0 = split * CHUNK;
    for (int i = t; i < CHUNK * DD; i += 256) {
        int j = i >> 6, d = i & 63;
        size_t gbase = ((size_t)(b * LL + key0 + j) * HH + h) << 6;
        Kt[d * 132 + j] = K[gbase + d];
        Vs[i]           = V[gbase + d];
    }
    __syncthreads();

    {
        int ublk = t >> 5;
        int jg   = t & 31;
        float4 acc[5];
#pragma unroll
        for (int k = 0; k < 5; k++) acc[k] = make_float4(0.f, 0.f, 0.f, 0.f);
        const float4* Kt4 = (const float4*)Kt;
#pragma unroll 8
        for (int d = 0; d < 64; d++) {
            float4 kv = Kt4[d * 33 + jg];
#pragma unroll
            for (int k = 0; k < 5; k++) {
                float qv = Qs[(ublk * 5 + k) * 64 + d];
                acc[k].x += qv * kv.x;
                acc[k].y += qv * kv.y;
                acc[k].z += qv * kv.z;
                acc[k].w += qv * kv.w;
            }
        }
#pragma unroll
        for (int k = 0; k < 5; k++) {
            int u = ublk * 5 + k;
            float4 sv = make_float4(acc[k].x * SCALE, acc[k].y * SCALE,
                                    acc[k].z * SCALE, acc[k].w * SCALE);
            *(float4*)(Ss + u * CHUNK + (jg << 2)) = sv;
        }
    }
    __syncthreads();

    {
        int w = t >> 5, lane = t & 31;
        for (int r = w * 5; r < w * 5 + 5; r++) {
            float v0 = Ss[r * CHUNK + lane];
            float v1 = Ss[r * CHUNK + lane + 32];
            float v2 = Ss[r * CHUNK + lane + 64];
            float v3 = Ss[r * CHUNK + lane + 96];
            float m = fmaxf(fmaxf(v0, v1), fmaxf(v2, v3));
#pragma unroll
            for (int o = 16; o; o >>= 1) m = fmaxf(m, __shfl_xor_sync(0xffffffffu, m, o));
            float e0 = __expf(v0 - m), e1 = __expf(v1 - m);
            float e2 = __expf(v2 - m), e3 = __expf(v3 - m);
            Ss[r * CHUNK + lane]      = e0;
            Ss[r * CHUNK + lane + 32] = e1;
            Ss[r * CHUNK + lane + 64] = e2;
            Ss[r * CHUNK + lane + 96] = e3;
            float s = e0 + e1 + e2 + e3;
#pragma unroll
            for (int o = 16; o; o >>= 1) s += __shfl_xor_sync(0xffffffffu, s, o);
            if (lane == 0) {
                g_pm[(bh * NSPLIT + split) * NT + r] = m;
                g_pl[(bh * NSPLIT + split) * NT + r] = s;
            }
        }
    }
    __syncthreads();

    {
        int ublk = t >> 5;
        int d4   = t & 15;
        int jh   = (t >> 4) & 1;
        float4 acc[5];
#pragma unroll
        for (int k = 0; k < 5; k++) acc[k] = make_float4(0.f, 0.f, 0.f, 0.f);
        const float4* Vs4 = (const float4*)Vs;
        int j0 = jh * 64;
#pragma unroll 4
        for (int jj = 0; jj < 64; jj++) {
            int j = j0 + jj;
            float4 vv = Vs4[j * 16 + d4];
#pragma unroll
            for (int k = 0; k < 5; k++) {
                float p = Ss[(ublk * 5 + k) * CHUNK + j];
                acc[k].x += p * vv.x;
                acc[k].y += p * vv.y;
                acc[k].z += p * vv.z;
                acc[k].w += p * vv.w;
            }
        }
        float* Opart = Kt;
#pragma unroll
        for (int k = 0; k < 5; k++) {
            int u = ublk * 5 + k;
            *(float4*)(Opart + (jh * NT + u) * 64 + (d4 << 2)) = acc[k];
        }
    }
    __syncthreads();

    for (int i = t; i < NT * DD; i += 256) {
        float v = Kt[i] + Kt[NT * DD + i];
        g_po[(size_t)(bh * NSPLIT + split) * NT * DD + i] = v;
    }
}

// ---------------- combine splits ----------------
__global__ void combine_kernel(float* __restrict__ out) {
    __shared__ float smx[NT], slx[NT];
    int bh = blockIdx.x, t = threadIdx.x;
    int b = bh >> 3, h = bh & 7;
    if (t < NT) {
        float m = -3e38f;
        for (int s = 0; s < NSPLIT; s++)
            m = fmaxf(m, g_pm[(bh * NSPLIT + s) * NT + t]);
        float Ls = 0.f;
        for (int s = 0; s < NSPLIT; s++)
            Ls += g_pl[(bh * NSPLIT + s) * NT + t] * __expf(g_pm[(bh * NSPLIT + s) * NT + t] - m);
        smx[t] = m; slx[t] = Ls;
    }
    __syncthreads();
    for (int i = t; i < NT * DD; i += 256) {
        int u = i >> 6, d = i & 63;
        float acc = 0.f;
        for (int s = 0; s < NSPLIT; s++) {
            float w = __expf(g_pm[(bh * NSPLIT + s) * NT + u] - smx[u]);
            acc += w * g_po[(size_t)(bh * NSPLIT + s) * NT * DD + i];
        }
        out[(((size_t)(b * NT + u) * HH + h) << 6) + d] = acc / slx[u];
    }
}

// ---------------- launcher ----------------
extern "C" void kernel_launch(void* const* d_in, const int* in_sizes, int n_in,
                              void* d_out, int out_size) {
    const float* Q   = (const float*)d_in[0];
    const float* K   = (const float*)d_in[1];
    const float* V   = (const float*)d_in[2];
    const void*  idx = d_in[3];

    detect_idx_kernel<<<1, 32>>>((const long long*)idx);
    zero_cnt_kernel<<<(NKC * LL) / 256, 256>>>();
    count_kernel<<<(LL * SK) / 256, 256>>>(idx);
    scan_kernel<<<NKC, 256>>>();
    scatter_kernel<<<(LL * SK) / 256, 256>>>(idx);

    size_t smemG = (size_t)CK * DD * sizeof(float);   // 98304 B
    cudaFuncSetAttribute(gather_dots_kernel, cudaFuncAttributeMaxDynamicSharedMemorySize, (int)smemG);
    gather_dots_kernel<<<BHN * NKC * LQ, 256, smemG>>>(Q, K);

    m_reduce_kernel<<<(BHN * LL) / 256, 256>>>();
    topk_kernel<<<BHN, 32>>>();

    size_t smemD = (size_t)(NT * DD + 64 * 132 + CHUNK * DD + NT * CHUNK) * sizeof(float);
    cudaFuncSetAttribute(attn_kernel, cudaFuncAttributeMaxDynamicSharedMemorySize, (int)smemD);
    attn_kernel<<<BHN * NSPLIT, 256, smemD>>>(Q, K, V);

    combine_kernel<<<BHN, 256>>>((float*)d_out);
}

// round 3
// speedup vs baseline: 2.1722x; 2.1722x over previous
#include <cuda_runtime.h>
#include <cstddef>

#define BB 4
#define LL 2048
#define HH 8
#define DD 64
#define SK 40
#define NT 40
#define BHN 32          // B*H
#define NSPLIT 16
#define CHUNK 128       // keys per split block in attn
#define SCALE 0.125f    // 1/sqrt(64)

// ---------------- scratch ----------------
__device__ int   g_is64;
__device__ float g_M[BHN * LL];
__device__ int   g_top[BHN * NT];
__device__ float g_pm[BHN * NSPLIT * NT];
__device__ float g_pl[BHN * NSPLIT * NT];
__device__ float g_po[BHN * NSPLIT * NT * DD];

// ---------------- detect index dtype (int64 vs int32) ----------------
__global__ void detect_idx_kernel(const long long* __restrict__ idx64) {
    int ok = 1;
    for (int i = threadIdx.x; i < 512; i += 32) {
        long long v = idx64[i];
        if (v < 0 || v >= LL) ok = 0;
    }
    unsigned m = __ballot_sync(0xffffffffu, ok);
    if (threadIdx.x == 0) g_is64 = (m == 0xffffffffu) ? 1 : 0;
}

// ---------------- sample_m v3: warp per (bh,l); 4 groups x 8 lanes ----------------
// group g handles sample s = 4r+g per round; lane covers 8 d's (2 x LDG.128).
// dot = 8 FMA + 3 shfl-xor (within 8-lane group). 3 shfl / 4 samples vs 5 / 1.
__global__ void sample_m_kernel(const float* __restrict__ Q,
                                const float* __restrict__ K,
                                const void*  __restrict__ idxbuf) {
    int wid  = (blockIdx.x * blockDim.x + threadIdx.x) >> 5;
    int lane = threadIdx.x & 31;
    int l  = wid % LL;
    int bh = wid / LL;
    int b = bh >> 3, h = bh & 7;
    int g  = lane >> 3;     // group 0..3
    int li = lane & 7;      // lane in group

    // preload sampled indices for this l into lane registers
    int ia = 0, ib = 0;
    if (g_is64) {
        const long long* p = (const long long*)idxbuf + (long long)l * SK;
        ia = (int)p[lane];
        if (lane < SK - 32) ib = (int)p[32 + lane];
    } else {
        const int* p = (const int*)idxbuf + l * SK;
        ia = p[lane];
        if (lane < SK - 32) ib = p[32 + lane];
    }

    // this lane's 8-d slice of q
    const float* qbase = Q + (((size_t)(b * LL + l) * HH + h) << 6) + (li << 3);
    const float4 qa = ((const float4*)qbase)[0];
    const float4 qb = ((const float4*)qbase)[1];

    const size_t kstride_h = ((size_t)h << 6) + ((size_t)li << 3);
    const float* Kb = K + ((size_t)b * LL * HH << 6);

    float mx = -3e38f, sm = 0.0f;
#pragma unroll
    for (int r = 0; r < 10; r++) {
        int s = 4 * r + g;
        int j = (s < 32) ? __shfl_sync(0xffffffffu, ia, s)
                         : __shfl_sync(0xffffffffu, ib, s - 32);
        const float4* kp = (const float4*)(Kb + (((size_t)j * HH) << 6) + kstride_h);
        float4 k0 = kp[0];
        float4 k1 = kp[1];
        float p = qa.x * k0.x;
        p = fmaf(qa.y, k0.y, p);
        p = fmaf(qa.z, k0.z, p);
        p = fmaf(qa.w, k0.w, p);
        p = fmaf(qb.x, k1.x, p);
        p = fmaf(qb.y, k1.y, p);
        p = fmaf(qb.z, k1.z, p);
        p = fmaf(qb.w, k1.w, p);
        p += __shfl_xor_sync(0xffffffffu, p, 1);
        p += __shfl_xor_sync(0xffffffffu, p, 2);
        p += __shfl_xor_sync(0xffffffffu, p, 4);
        mx = fmaxf(mx, p);
        sm += p;
    }
    // cross-group combine (all lanes in a group hold identical values)
    mx = fmaxf(mx, __shfl_xor_sync(0xffffffffu, mx, 8));
    mx = fmaxf(mx, __shfl_xor_sync(0xffffffffu, mx, 16));
    sm += __shfl_xor_sync(0xffffffffu, sm, 8);
    sm += __shfl_xor_sync(0xffffffffu, sm, 16);
    if (lane == 0) g_M[bh * LL + l] = mx - sm * (1.0f / (float)LL);
}

// ---------------- top-40 per bh: warp kernel, tie -> lower index ----------------
__global__ void topk_kernel() {
    __shared__ float sM[LL];
    int bh = blockIdx.x, lane = threadIdx.x;       // 32 threads
    for (int i = lane; i < LL; i += 32) sM[i] = g_M[bh * LL + i];
    __syncwarp();

    float bv = -3e38f; int bi = lane * 64;
    for (int i = 0; i < 64; i++) {
        float x = sM[lane * 64 + i];
        if (x > bv) { bv = x; bi = lane * 64 + i; }
    }
    for (int it = 0; it < NT; it++) {
        unsigned uv = __float_as_uint(bv);
        uv ^= (uv >> 31) ? 0xffffffffu : 0x80000000u;
        unsigned long long key = ((unsigned long long)uv << 32) | (unsigned)(LL - 1 - bi);
#pragma unroll
        for (int o = 16; o; o >>= 1) {
            unsigned long long ok = __shfl_xor_sync(0xffffffffu, key, o);
            if (ok > key) key = ok;
        }
        int wi = LL - 1 - (int)(key & 0xffffffffu);
        if (lane == 0) { g_top[bh * NT + it] = wi; sM[wi] = -3e38f; }
        __syncwarp();

        int seg = wi >> 6;
        float x0 = sM[(seg << 6) + lane];
        float x1 = sM[(seg << 6) + 32 + lane];
        float rv; int ri;
        if (x0 >= x1) { rv = x0; ri = (seg << 6) + lane; }
        else          { rv = x1; ri = (seg << 6) + 32 + lane; }
        unsigned ru = __float_as_uint(rv);
        ru ^= (ru >> 31) ? 0xffffffffu : 0x80000000u;
        unsigned long long rkey = ((unsigned long long)ru << 32) | (unsigned)(LL - 1 - ri);
#pragma unroll
        for (int o = 16; o; o >>= 1) {
            unsigned long long ok = __shfl_xor_sync(0xffffffffu, rkey, o);
            if (ok > rkey) rkey = ok;
        }
        if (lane == seg) {
            unsigned nu = (unsigned)(rkey >> 32);
            nu = (nu & 0x80000000u) ? (nu ^ 0x80000000u) : ~nu;
            bv = __uint_as_float(nu);
            bi = LL - 1 - (int)(rkey & 0xffffffffu);
        }
        __syncwarp();
    }
}

// ---------------- split-K attention (unchanged from R1) ----------------
__global__ void attn_kernel(const float* __restrict__ Q,
                            const float* __restrict__ K,
                            const float* __restrict__ V) {
    extern __shared__ float smem[];
    int bh = blockIdx.x / NSPLIT, split = blockIdx.x % NSPLIT;
    int b = bh >> 3, h = bh & 7;
    int t = threadIdx.x;

    float* Qs = smem;
    float* Kt = Qs + NT * DD;
    float* Vs = Kt + 64 * 132;
    float* Ss = Vs + CHUNK * DD;

    for (int i = t; i < NT * DD; i += 256) {
        int u = i >> 6, d = i & 63;
        int ql = g_top[bh * NT + u];
        Qs[i] = Q[(((size_t)(b * LL + ql) * HH + h) << 6) + d];
    }
    int key0 = split * CHUNK;
    for (int i = t; i < CHUNK * DD; i += 256) {
        int j = i >> 6, d = i & 63;
        size_t gbase = ((size_t)(b * LL + key0 + j) * HH + h) << 6;
        Kt[d * 132 + j] = K[gbase + d];
        Vs[i]           = V[gbase + d];
    }
    __syncthreads();

    {
        int ublk = t >> 5;
        int jg   = t & 31;
        float4 acc[5];
#pragma unroll
        for (int k = 0; k < 5; k++) acc[k] = make_float4(0.f, 0.f, 0.f, 0.f);
        const float4* Kt4 = (const float4*)Kt;
#pragma unroll 8
        for (int d = 0; d < 64; d++) {
            float4 kv = Kt4[d * 33 + jg];
#pragma unroll
            for (int k = 0; k < 5; k++) {
                float qv = Qs[(ublk * 5 + k) * 64 + d];
                acc[k].x += qv * kv.x;
                acc[k].y += qv * kv.y;
                acc[k].z += qv * kv.z;
                acc[k].w += qv * kv.w;
            }
        }
#pragma unroll
        for (int k = 0; k < 5; k++) {
            int u = ublk * 5 + k;
            float4 sv = make_float4(acc[k].x * SCALE, acc[k].y * SCALE,
                                    acc[k].z * SCALE, acc[k].w * SCALE);
            *(float4*)(Ss + u * CHUNK + (jg << 2)) = sv;
        }
    }
    __syncthreads();

    {
        int w = t >> 5, lane = t & 31;
        for (int r = w * 5; r < w * 5 + 5; r++) {
            float v0 = Ss[r * CHUNK + lane];
            float v1 = Ss[r * CHUNK + lane + 32];
            float v2 = Ss[r * CHUNK + lane + 64];
            float v3 = Ss[r * CHUNK + lane + 96];
            float m = fmaxf(fmaxf(v0, v1), fmaxf(v2, v3));
#pragma unroll
            for (int o = 16; o; o >>= 1) m = fmaxf(m, __shfl_xor_sync(0xffffffffu, m, o));
            float e0 = __expf(v0 - m), e1 = __expf(v1 - m);
            float e2 = __expf(v2 - m), e3 = __expf(v3 - m);
            Ss[r * CHUNK + lane]      = e0;
            Ss[r * CHUNK + lane + 32] = e1;
            Ss[r * CHUNK + lane + 64] = e2;
            Ss[r * CHUNK + lane + 96] = e3;
            float s = e0 + e1 + e2 + e3;
#pragma unroll
            for (int o = 16; o; o >>= 1) s += __shfl_xor_sync(0xffffffffu, s, o);
            if (lane == 0) {
                g_pm[(bh * NSPLIT + split) * NT + r] = m;
                g_pl[(bh * NSPLIT + split) * NT + r] = s;
            }
        }
    }
    __syncthreads();

    {
        int ublk = t >> 5;
        int d4   = t & 15;
        int jh   = (t >> 4) & 1;
        float4 acc[5];
#pragma unroll
        for (int k = 0; k < 5; k++) acc[k] = make_float4(0.f, 0.f, 0.f, 0.f);
        const float4* Vs4 = (const float4*)Vs;
        int j0 = jh * 64;
#pragma unroll 4
        for (int jj = 0; jj < 64; jj++) {
            int j = j0 + jj;
            float4 vv = Vs4[j * 16 + d4];
#pragma unroll
            for (int k = 0; k < 5; k++) {
                float p = Ss[(ublk * 5 + k) * CHUNK + j];
                acc[k].x += p * vv.x;
                acc[k].y += p * vv.y;
                acc[k].z += p * vv.z;
                acc[k].w += p * vv.w;
            }
        }
        float* Opart = Kt;
#pragma unroll
        for (int k = 0; k < 5; k++) {
            int u = ublk * 5 + k;
            *(float4*)(Opart + (jh * NT + u) * 64 + (d4 << 2)) = acc[k];
        }
    }
    __syncthreads();

    for (int i = t; i < NT * DD; i += 256) {
        float v = Kt[i] + Kt[NT * DD + i];
        g_po[(size_t)(bh * NSPLIT + split) * NT * DD + i] = v;
    }
}

// ---------------- combine splits ----------------
__global__ void combine_kernel(float* __restrict__ out) {
    __shared__ float smx[NT], slx[NT];
    int bh = blockIdx.x, t = threadIdx.x;
    int b = bh >> 3, h = bh & 7;
    if (t < NT) {
        float m = -3e38f;
        for (int s = 0; s < NSPLIT; s++)
            m = fmaxf(m, g_pm[(bh * NSPLIT + s) * NT + t]);
        float Ls = 0.f;
        for (int s = 0; s < NSPLIT; s++)
            Ls += g_pl[(bh * NSPLIT + s) * NT + t] * __expf(g_pm[(bh * NSPLIT + s) * NT + t] - m);
        smx[t] = m; slx[t] = Ls;
    }
    __syncthreads();
    for (int i = t; i < NT * DD; i += 256) {
        int u = i >> 6, d = i & 63;
        float acc = 0.f;
        for (int s = 0; s < NSPLIT; s++) {
            float w = __expf(g_pm[(bh * NSPLIT + s) * NT + u] - smx[u]);
            acc += w * g_po[(size_t)(bh * NSPLIT + s) * NT * DD + i];
        }
        out[(((size_t)(b * NT + u) * HH + h) << 6) + d] = acc / slx[u];
    }
}

// ---------------- launcher ----------------
extern "C" void kernel_launch(void* const* d_in, const int* in_sizes, int n_in,
                              void* d_out, int out_size) {
    const float* Q   = (const float*)d_in[0];
    const float* K   = (const float*)d_in[1];
    const float* V   = (const float*)d_in[2];
    const void*  idx = d_in[3];

    detect_idx_kernel<<<1, 32>>>((const long long*)idx);
    sample_m_kernel<<<(BHN * LL) / 8, 256>>>(Q, K, idx);
    topk_kernel<<<BHN, 32>>>();

    size_t smemD = (size_t)(NT * DD + 64 * 132 + CHUNK * DD + NT * CHUNK) * sizeof(float);
    cudaFuncSetAttribute(attn_kernel, cudaFuncAttributeMaxDynamicSharedMemorySize, (int)smemD);
    attn_kernel<<<BHN * NSPLIT, 256, smemD>>>(Q, K, V);

    combine_kernel<<<BHN, 256>>>((float*)d_out);
}